// round 1
// baseline (speedup 1.0000x reference)
#include <cuda_runtime.h>
#include <cstdint>
#include <cstddef>

// ---------------------------------------------------------------------------
// SamplingBottleneckModule:
//   logits1 = x @ w_both^T ; probs = softmax(logits1)
//   logits2 = x @ w_values^T ; values = softmax(probs + logits2)
//   alpha: 3-step Newton s.t. sum(1 - (1-p)^alpha) = K (K=8)
//   marginals = 1 - (1-p)^alpha
//   cumsum = exclusive cumsum(probs)
// Shapes: x (32768, 512) f32, w (512, 512) f32 each.
// Output: [marginals | values | cumsum], each 32768x512 f32.
// ---------------------------------------------------------------------------

#define ROWS_TOTAL 32768
#define NCLS 512
#define KDIM 512
#define NFUSED 1024   // both GEMMs stacked on the N axis
#define KSEQ 8.0f     // Newton target K

// Scratch for fused logits (32768 x 1024 f32 = 128 MiB). __device__ global
// (no runtime allocation allowed).
__device__ float g_logits[(size_t)ROWS_TOTAL * NFUSED];

// ---------------------------------------------------------------------------
// Kernel 1: fused SGEMM  C[m][n] = sum_k X[m][k] * W[n][k]
//   W = concat(w_both, w_values) along n (n<512 -> w_both)
// 128x128 block tile, BK=16, 256 threads, 8x8 per-thread tile.
// ---------------------------------------------------------------------------
__global__ __launch_bounds__(256, 2)
void gemm_fused_kernel(const float* __restrict__ X,
                       const float* __restrict__ WB,
                       const float* __restrict__ WV)
{
    __shared__ float As[16][128];   // As[k][m]
    __shared__ float Bs[16][128];   // Bs[k][n]

    const int tid = threadIdx.x;
    const int m0 = blockIdx.y * 128;
    const int n0 = blockIdx.x * 128;

    const int lr = tid >> 2;          // 0..63 (row within tile, +64 second pass)
    const int lc = (tid & 3) << 2;    // k-offset within BK: 0,4,8,12
    const int tx = tid & 15;          // col group
    const int ty = tid >> 4;          // row group

    float acc[8][8];
#pragma unroll
    for (int i = 0; i < 8; i++)
#pragma unroll
        for (int j = 0; j < 8; j++) acc[i][j] = 0.0f;

    for (int k0 = 0; k0 < KDIM; k0 += 16) {
        // Stage A tile (transposed into As[k][m])
#pragma unroll
        for (int r = 0; r < 2; r++) {
            const int row = lr + r * 64;
            const float4 v = *reinterpret_cast<const float4*>(
                X + (size_t)(m0 + row) * KDIM + k0 + lc);
            As[lc + 0][row] = v.x;
            As[lc + 1][row] = v.y;
            As[lc + 2][row] = v.z;
            As[lc + 3][row] = v.w;
        }
        // Stage B tile (transposed into Bs[k][n]); pick weight matrix per n
#pragma unroll
        for (int r = 0; r < 2; r++) {
            const int nrow = lr + r * 64;
            const int n = n0 + nrow;
            const float* wp = (n < NCLS) ? (WB + (size_t)n * KDIM)
                                         : (WV + (size_t)(n - NCLS) * KDIM);
            const float4 v = *reinterpret_cast<const float4*>(wp + k0 + lc);
            Bs[lc + 0][nrow] = v.x;
            Bs[lc + 1][nrow] = v.y;
            Bs[lc + 2][nrow] = v.z;
            Bs[lc + 3][nrow] = v.w;
        }
        __syncthreads();

#pragma unroll
        for (int k = 0; k < 16; k++) {
            float a[8], b[8];
            *reinterpret_cast<float4*>(&a[0]) =
                *reinterpret_cast<const float4*>(&As[k][ty * 8]);
            *reinterpret_cast<float4*>(&a[4]) =
                *reinterpret_cast<const float4*>(&As[k][ty * 8 + 4]);
            *reinterpret_cast<float4*>(&b[0]) =
                *reinterpret_cast<const float4*>(&Bs[k][tx * 8]);
            *reinterpret_cast<float4*>(&b[4]) =
                *reinterpret_cast<const float4*>(&Bs[k][tx * 8 + 4]);
#pragma unroll
            for (int i = 0; i < 8; i++)
#pragma unroll
                for (int j = 0; j < 8; j++)
                    acc[i][j] = fmaf(a[i], b[j], acc[i][j]);
        }
        __syncthreads();
    }

    // Write tile to scratch logits
    float* C = g_logits + (size_t)(m0 + ty * 8) * NFUSED + n0 + tx * 8;
#pragma unroll
    for (int i = 0; i < 8; i++) {
        *reinterpret_cast<float4*>(C + (size_t)i * NFUSED) =
            make_float4(acc[i][0], acc[i][1], acc[i][2], acc[i][3]);
        *reinterpret_cast<float4*>(C + (size_t)i * NFUSED + 4) =
            make_float4(acc[i][4], acc[i][5], acc[i][6], acc[i][7]);
    }
}

// ---------------------------------------------------------------------------
// Kernel 2: per-row epilogue. One warp per row; 16 classes per lane
// (class = lane + 32*i). All reductions via warp shuffles.
// ---------------------------------------------------------------------------
__global__ __launch_bounds__(256)
void epilogue_kernel(float* __restrict__ out)
{
    const int warp = threadIdx.x >> 5;
    const int lane = threadIdx.x & 31;
    const int row = blockIdx.x * 8 + warp;
    if (row >= ROWS_TOTAL) return;

    const float* lrow = g_logits + (size_t)row * NFUSED;

    float l1[16], l2[16];
#pragma unroll
    for (int i = 0; i < 16; i++) {
        l1[i] = lrow[i * 32 + lane];
        l2[i] = lrow[NCLS + i * 32 + lane];
    }

    // ---- softmax over logits1 -> probs p ----
    float mx = l1[0];
#pragma unroll
    for (int i = 1; i < 16; i++) mx = fmaxf(mx, l1[i]);
#pragma unroll
    for (int o = 16; o > 0; o >>= 1)
        mx = fmaxf(mx, __shfl_xor_sync(0xFFFFFFFFu, mx, o));

    float p[16];
    float s = 0.0f;
#pragma unroll
    for (int i = 0; i < 16; i++) {
        p[i] = expf(l1[i] - mx);
        s += p[i];
    }
#pragma unroll
    for (int o = 16; o > 0; o >>= 1)
        s += __shfl_xor_sync(0xFFFFFFFFu, s, o);
    const float inv = 1.0f / s;
#pragma unroll
    for (int i = 0; i < 16; i++) p[i] *= inv;

    // ---- values = softmax(p + logits2) ----
#pragma unroll
    for (int i = 0; i < 16; i++) l2[i] = p[i] + l2[i];
    float mx2 = l2[0];
#pragma unroll
    for (int i = 1; i < 16; i++) mx2 = fmaxf(mx2, l2[i]);
#pragma unroll
    for (int o = 16; o > 0; o >>= 1)
        mx2 = fmaxf(mx2, __shfl_xor_sync(0xFFFFFFFFu, mx2, o));
    float s2 = 0.0f;
#pragma unroll
    for (int i = 0; i < 16; i++) {
        l1[i] = expf(l2[i] - mx2);   // reuse l1 as exp buffer
        s2 += l1[i];
    }
#pragma unroll
    for (int o = 16; o > 0; o >>= 1)
        s2 += __shfl_xor_sync(0xFFFFFFFFu, s2, o);
    const float inv2 = 1.0f / s2;
#pragma unroll
    for (int i = 0; i < 16; i++) l1[i] *= inv2;   // l1 = values

    // ---- Newton solve for alpha (3 iterations, init K) ----
    float y[16];
#pragma unroll
    for (int i = 0; i < 16; i++) y[i] = logf(1.0f - p[i]);

    float alpha = KSEQ;
#pragma unroll
    for (int it = 0; it < 3; it++) {
        float se = 0.0f, sd = 0.0f;
#pragma unroll
        for (int i = 0; i < 16; i++) {
            const float e = expf(alpha * y[i]);
            se += e;
            sd += e * y[i];
        }
#pragma unroll
        for (int o = 16; o > 0; o >>= 1) {
            se += __shfl_xor_sync(0xFFFFFFFFu, se, o);
            sd += __shfl_xor_sync(0xFFFFFFFFu, sd, o);
        }
        alpha -= (se + (KSEQ - (float)NCLS)) / sd;
    }

    // ---- marginals = 1 - exp(alpha * y) ----
#pragma unroll
    for (int i = 0; i < 16; i++) l2[i] = 1.0f - expf(alpha * y[i]);  // l2 = marginals

    const size_t BTN = (size_t)ROWS_TOTAL * NCLS;
    float* om = out;
    float* ov = out + BTN;
    float* oc = out + 2 * BTN;
    const size_t base = (size_t)row * NCLS;

#pragma unroll
    for (int i = 0; i < 16; i++) {
        om[base + i * 32 + lane] = l2[i];
        ov[base + i * 32 + lane] = l1[i];
    }

    // ---- exclusive cumsum of p over class order (lane + 32*i) ----
    float run = 0.0f;
#pragma unroll
    for (int i = 0; i < 16; i++) {
        const float v = p[i];
        float c = v;
#pragma unroll
        for (int o = 1; o < 32; o <<= 1) {
            const float nv = __shfl_up_sync(0xFFFFFFFFu, c, o);
            if (lane >= o) c += nv;
        }
        oc[base + i * 32 + lane] = run + c - v;
        run += __shfl_sync(0xFFFFFFFFu, c, 31);
    }
}

// ---------------------------------------------------------------------------
extern "C" void kernel_launch(void* const* d_in, const int* in_sizes, int n_in,
                              void* d_out, int out_size)
{
    const float* x  = (const float*)d_in[0];
    const float* wb = (const float*)d_in[1];
    const float* wv = (const float*)d_in[2];
    float* out = (float*)d_out;

    (void)n_in; (void)out_size; (void)in_sizes;

    dim3 g1(NFUSED / 128, ROWS_TOTAL / 128);   // (8, 256)
    gemm_fused_kernel<<<g1, 256>>>(x, wb, wv);

    epilogue_kernel<<<ROWS_TOTAL / 8, 256>>>(out);
}

// round 3
// speedup vs baseline: 2.4141x; 2.4141x over previous
#include <cuda_runtime.h>
#include <cuda_bf16.h>
#include <cstdint>
#include <cstddef>

// ---------------------------------------------------------------------------
// SamplingBottleneckModule on GB300 — legacy HMMA (mma.sync) bf16
// split-precision GEMM (PTX target is base sm_103: no tcgen05 available).
//   logits = x @ [w_both | w_values]^T  via 3-term bf16 split:
//       x*w ~= x_hi*w_hi + x_lo*w_hi + x_hi*w_lo   (fp32 accum)
//   then per-row epilogue (softmax x2, Newton alpha, marginals, excl-cumsum)
// ---------------------------------------------------------------------------

#define ROWS_TOTAL 32768
#define NCLS 512
#define KDIM 512
#define NFUSED 1024
#define KSEQ 8.0f

// Scratch (device globals; no runtime allocation allowed)
__device__ float g_logits[(size_t)ROWS_TOTAL * NFUSED];                    // 128 MiB
__device__ __align__(256) __nv_bfloat162 g_ahi[(size_t)ROWS_TOTAL * 256];  // 32 MiB
__device__ __align__(256) __nv_bfloat162 g_alo[(size_t)ROWS_TOTAL * 256];  // 32 MiB
__device__ __align__(256) __nv_bfloat162 g_bhi[(size_t)NFUSED * 256];      // 1 MiB
__device__ __align__(256) __nv_bfloat162 g_blo[(size_t)NFUSED * 256];      // 1 MiB

// ---------------------------------------------------------------------------
// Helpers
// ---------------------------------------------------------------------------
__device__ __forceinline__ uint32_t smem_u32(const void* p) {
    uint32_t a;
    asm("{ .reg .u64 t; cvta.to.shared.u64 t, %1; cvt.u32.u64 %0, t; }"
        : "=r"(a) : "l"(p));
    return a;
}
__device__ __forceinline__ void cp16(uint32_t dst, const void* src) {
    asm volatile("cp.async.cg.shared.global [%0], [%1], 16;"
                 :: "r"(dst), "l"(src) : "memory");
}
__device__ __forceinline__ void ldsm4(uint32_t* r, uint32_t addr) {
    asm volatile("ldmatrix.sync.aligned.m8n8.x4.shared.b16 {%0,%1,%2,%3}, [%4];"
                 : "=r"(r[0]), "=r"(r[1]), "=r"(r[2]), "=r"(r[3]) : "r"(addr));
}
__device__ __forceinline__ void mma_bf16(float* c, const uint32_t* a,
                                         const uint32_t* b) {
    asm volatile(
        "mma.sync.aligned.m16n8k16.row.col.f32.bf16.bf16.f32 "
        "{%0,%1,%2,%3},{%4,%5,%6,%7},{%8,%9},{%0,%1,%2,%3};"
        : "+f"(c[0]), "+f"(c[1]), "+f"(c[2]), "+f"(c[3])
        : "r"(a[0]), "r"(a[1]), "r"(a[2]), "r"(a[3]), "r"(b[0]), "r"(b[1]));
}

// ---------------------------------------------------------------------------
// Convert kernels: fp32 -> (hi, lo) bf16 split.
// ---------------------------------------------------------------------------
__global__ __launch_bounds__(256)
void convert_x_kernel(const float* __restrict__ X)
{
    size_t idx = (size_t)blockIdx.x * 256 + threadIdx.x;   // float2 index
    float2 v = reinterpret_cast<const float2*>(X)[idx];
    __nv_bfloat16 h0 = __float2bfloat16(v.x);
    __nv_bfloat16 h1 = __float2bfloat16(v.y);
    __nv_bfloat162 hp; hp.x = h0; hp.y = h1;
    __nv_bfloat162 lp;
    lp.x = __float2bfloat16(v.x - __bfloat162float(h0));
    lp.y = __float2bfloat16(v.y - __bfloat162float(h1));
    g_ahi[idx] = hp;
    g_alo[idx] = lp;
}

__global__ __launch_bounds__(256)
void convert_w_kernel(const float* __restrict__ WB, const float* __restrict__ WV)
{
    size_t idx = (size_t)blockIdx.x * 256 + threadIdx.x;
    int n = (int)(idx >> 8);
    int c2 = (int)(idx & 255);
    const float* src = (n < NCLS) ? (WB + (size_t)n * KDIM)
                                  : (WV + (size_t)(n - NCLS) * KDIM);
    float2 v = reinterpret_cast<const float2*>(src)[c2];
    __nv_bfloat16 h0 = __float2bfloat16(v.x);
    __nv_bfloat16 h1 = __float2bfloat16(v.y);
    __nv_bfloat162 hp; hp.x = h0; hp.y = h1;
    __nv_bfloat162 lp;
    lp.x = __float2bfloat16(v.x - __bfloat162float(h0));
    lp.y = __float2bfloat16(v.y - __bfloat162float(h1));
    g_bhi[idx] = hp;
    g_blo[idx] = lp;
}

// ---------------------------------------------------------------------------
// HMMA GEMM: 128x128 CTA tile, BK=32, double-buffered cp.async.
// 8 warps as 2(m) x 4(n); warp tile 64x32 -> 4x4 m16n8 acc tiles.
// 3 split terms accumulate into the same fp32 acc.
// ---------------------------------------------------------------------------
#define BK 32
#define NIT (KDIM / BK)            // 16
#define RB 80                      // smem row stride in bytes (40 bf16)
#define MATB (128 * RB)            // 10240 bytes per matrix tile
#define STAGEB (4 * MATB)          // 40960 bytes per stage
#define SMEM_GEMM (2 * STAGEB)     // 81920

__device__ __forceinline__ void load_stage(uint32_t sb, int s, int it,
                                           int m0, int n0, int tid)
{
    const int k0 = it * BK;
    const char* ah = (const char*)g_ahi;
    const char* al = (const char*)g_alo;
    const char* bh = (const char*)g_bhi;
    const char* bl = (const char*)g_blo;
    const uint32_t stb = sb + s * STAGEB;

#pragma unroll
    for (int mat = 0; mat < 4; mat++) {
#pragma unroll
        for (int half = 0; half < 2; half++) {
            const int ci = tid + half * 256;      // 0..511
            const int row = ci >> 2;
            const int seg = ci & 3;
            const char* base;
            size_t grow;
            if (mat == 0)      { base = ah; grow = (size_t)(m0 + row); }
            else if (mat == 1) { base = al; grow = (size_t)(m0 + row); }
            else if (mat == 2) { base = bh; grow = (size_t)(n0 + row); }
            else               { base = bl; grow = (size_t)(n0 + row); }
            const char* src = base + (grow * KDIM + k0) * 2 + seg * 16;
            const uint32_t dst = stb + mat * MATB + row * RB + seg * 16;
            cp16(dst, src);
        }
    }
    asm volatile("cp.async.commit_group;" ::: "memory");
}

__global__ __launch_bounds__(256, 2)
void gemm_hmma_kernel()
{
    extern __shared__ char smem[];
    const uint32_t sb = smem_u32(smem);
    const int tid = threadIdx.x;
    const int lane = tid & 31;
    const int wid = tid >> 5;
    const int m0 = blockIdx.y * 128;
    const int n0 = blockIdx.x * 128;
    const int wm = (wid >> 2) * 64;     // warp m offset in tile
    const int wn = (wid & 3) * 32;      // warp n offset in tile

    // Per-lane ldmatrix address components (byte offsets within a matrix tile)
    const uint32_t aoff = (uint32_t)((wm + (lane & 15)) * RB + ((lane >> 4) << 4));
    const uint32_t boff = (uint32_t)((wn + (lane & 7) + ((lane >> 4) << 3)) * RB
                                     + (((lane >> 3) & 1) << 4));

    float acc[4][4][4];
#pragma unroll
    for (int i = 0; i < 4; i++)
#pragma unroll
        for (int j = 0; j < 4; j++)
#pragma unroll
            for (int r = 0; r < 4; r++) acc[i][j][r] = 0.0f;

    load_stage(sb, 0, 0, m0, n0, tid);
    load_stage(sb, 1, 1, m0, n0, tid);

#pragma unroll 1
    for (int it = 0; it < NIT; it++) {
        const int s = it & 1;
        asm volatile("cp.async.wait_group 1;" ::: "memory");
        __syncthreads();

        const uint32_t Ah = sb + s * STAGEB + aoff;
        const uint32_t Al = Ah + MATB;
        const uint32_t Bh = sb + s * STAGEB + 2 * MATB + boff;
        const uint32_t Bl = Bh + MATB;

#pragma unroll
        for (int kk = 0; kk < 2; kk++) {
            const uint32_t kb = kk << 5;        // 0 or 32 bytes (k16 step)
            uint32_t a[4][4], b[4][2];

            // term 1: a_hi * b_hi
#pragma unroll
            for (int i = 0; i < 4; i++) ldsm4(a[i], Ah + i * (16 * RB) + kb);
#pragma unroll
            for (int jj = 0; jj < 2; jj++) {
                uint32_t r[4];
                ldsm4(r, Bh + jj * (16 * RB) + kb);
                b[2 * jj][0] = r[0]; b[2 * jj][1] = r[1];
                b[2 * jj + 1][0] = r[2]; b[2 * jj + 1][1] = r[3];
            }
#pragma unroll
            for (int i = 0; i < 4; i++)
#pragma unroll
                for (int j = 0; j < 4; j++) mma_bf16(acc[i][j], a[i], b[j]);

            // term 2: a_hi * b_lo (reuse a)
#pragma unroll
            for (int jj = 0; jj < 2; jj++) {
                uint32_t r[4];
                ldsm4(r, Bl + jj * (16 * RB) + kb);
                b[2 * jj][0] = r[0]; b[2 * jj][1] = r[1];
                b[2 * jj + 1][0] = r[2]; b[2 * jj + 1][1] = r[3];
            }
#pragma unroll
            for (int i = 0; i < 4; i++)
#pragma unroll
                for (int j = 0; j < 4; j++) mma_bf16(acc[i][j], a[i], b[j]);

            // term 3: a_lo * b_hi (reload both)
#pragma unroll
            for (int i = 0; i < 4; i++) ldsm4(a[i], Al + i * (16 * RB) + kb);
#pragma unroll
            for (int jj = 0; jj < 2; jj++) {
                uint32_t r[4];
                ldsm4(r, Bh + jj * (16 * RB) + kb);
                b[2 * jj][0] = r[0]; b[2 * jj][1] = r[1];
                b[2 * jj + 1][0] = r[2]; b[2 * jj + 1][1] = r[3];
            }
#pragma unroll
            for (int i = 0; i < 4; i++)
#pragma unroll
                for (int j = 0; j < 4; j++) mma_bf16(acc[i][j], a[i], b[j]);
        }

        __syncthreads();
        if (it + 2 < NIT) {
            load_stage(sb, s, it + 2, m0, n0, tid);
        } else {
            asm volatile("cp.async.commit_group;" ::: "memory");  // keep count
        }
    }

    // Write accumulators to g_logits
    const int rbase = m0 + wm + (lane >> 2);
    const int cbase = n0 + wn + 2 * (lane & 3);
#pragma unroll
    for (int i = 0; i < 4; i++) {
#pragma unroll
        for (int j = 0; j < 4; j++) {
            const int r = rbase + i * 16;
            const int c = cbase + j * 8;
            float2 v0 = make_float2(acc[i][j][0], acc[i][j][1]);
            float2 v1 = make_float2(acc[i][j][2], acc[i][j][3]);
            *reinterpret_cast<float2*>(g_logits + (size_t)r * NFUSED + c) = v0;
            *reinterpret_cast<float2*>(g_logits + (size_t)(r + 8) * NFUSED + c) = v1;
        }
    }
}

// ---------------------------------------------------------------------------
// Per-row epilogue: one warp per row (same as round 1, verified correct).
// ---------------------------------------------------------------------------
__global__ __launch_bounds__(256)
void epilogue_kernel(float* __restrict__ out)
{
    const int warp = threadIdx.x >> 5;
    const int lane = threadIdx.x & 31;
    const int row = blockIdx.x * 8 + warp;
    if (row >= ROWS_TOTAL) return;

    const float* lrow = g_logits + (size_t)row * NFUSED;

    float l1[16], l2[16];
#pragma unroll
    for (int i = 0; i < 16; i++) {
        l1[i] = lrow[i * 32 + lane];
        l2[i] = lrow[NCLS + i * 32 + lane];
    }

    float mx = l1[0];
#pragma unroll
    for (int i = 1; i < 16; i++) mx = fmaxf(mx, l1[i]);
#pragma unroll
    for (int o = 16; o > 0; o >>= 1)
        mx = fmaxf(mx, __shfl_xor_sync(0xFFFFFFFFu, mx, o));

    float p[16];
    float s = 0.0f;
#pragma unroll
    for (int i = 0; i < 16; i++) {
        p[i] = expf(l1[i] - mx);
        s += p[i];
    }
#pragma unroll
    for (int o = 16; o > 0; o >>= 1)
        s += __shfl_xor_sync(0xFFFFFFFFu, s, o);
    const float inv = 1.0f / s;
#pragma unroll
    for (int i = 0; i < 16; i++) p[i] *= inv;

#pragma unroll
    for (int i = 0; i < 16; i++) l2[i] = p[i] + l2[i];
    float mx2 = l2[0];
#pragma unroll
    for (int i = 1; i < 16; i++) mx2 = fmaxf(mx2, l2[i]);
#pragma unroll
    for (int o = 16; o > 0; o >>= 1)
        mx2 = fmaxf(mx2, __shfl_xor_sync(0xFFFFFFFFu, mx2, o));
    float s2 = 0.0f;
#pragma unroll
    for (int i = 0; i < 16; i++) {
        l1[i] = expf(l2[i] - mx2);
        s2 += l1[i];
    }
#pragma unroll
    for (int o = 16; o > 0; o >>= 1)
        s2 += __shfl_xor_sync(0xFFFFFFFFu, s2, o);
    const float inv2 = 1.0f / s2;
#pragma unroll
    for (int i = 0; i < 16; i++) l1[i] *= inv2;   // values

    float y[16];
#pragma unroll
    for (int i = 0; i < 16; i++) y[i] = logf(1.0f - p[i]);

    float alpha = KSEQ;
#pragma unroll
    for (int it = 0; it < 3; it++) {
        float se = 0.0f, sd = 0.0f;
#pragma unroll
        for (int i = 0; i < 16; i++) {
            const float e = expf(alpha * y[i]);
            se += e;
            sd += e * y[i];
        }
#pragma unroll
        for (int o = 16; o > 0; o >>= 1) {
            se += __shfl_xor_sync(0xFFFFFFFFu, se, o);
            sd += __shfl_xor_sync(0xFFFFFFFFu, sd, o);
        }
        alpha -= (se + (KSEQ - (float)NCLS)) / sd;
    }

#pragma unroll
    for (int i = 0; i < 16; i++) l2[i] = 1.0f - expf(alpha * y[i]);  // marginals

    const size_t BTN = (size_t)ROWS_TOTAL * NCLS;
    float* om = out;
    float* ov = out + BTN;
    float* oc = out + 2 * BTN;
    const size_t base = (size_t)row * NCLS;

#pragma unroll
    for (int i = 0; i < 16; i++) {
        om[base + i * 32 + lane] = l2[i];
        ov[base + i * 32 + lane] = l1[i];
    }

    float run = 0.0f;
#pragma unroll
    for (int i = 0; i < 16; i++) {
        const float v = p[i];
        float c = v;
#pragma unroll
        for (int o = 1; o < 32; o <<= 1) {
            const float nv = __shfl_up_sync(0xFFFFFFFFu, c, o);
            if (lane >= o) c += nv;
        }
        oc[base + i * 32 + lane] = run + c - v;
        run += __shfl_sync(0xFFFFFFFFu, c, 31);
    }
}

// ---------------------------------------------------------------------------
extern "C" void kernel_launch(void* const* d_in, const int* in_sizes, int n_in,
                              void* d_out, int out_size)
{
    const float* x  = (const float*)d_in[0];
    const float* wb = (const float*)d_in[1];
    const float* wv = (const float*)d_in[2];
    float* out = (float*)d_out;
    (void)n_in; (void)out_size; (void)in_sizes;

    static bool configured = false;
    if (!configured) {
        cudaFuncSetAttribute(gemm_hmma_kernel,
                             cudaFuncAttributeMaxDynamicSharedMemorySize,
                             SMEM_GEMM);
        configured = true;
    }

    convert_w_kernel<<<(NFUSED * 256) / 256, 256>>>(wb, wv);
    convert_x_kernel<<<((size_t)ROWS_TOTAL * 256) / 256, 256>>>(x);

    dim3 grid(NFUSED / 128, ROWS_TOTAL / 128);   // (8, 256)
    gemm_hmma_kernel<<<grid, 256, SMEM_GEMM>>>();

    epilogue_kernel<<<ROWS_TOTAL / 8, 256>>>(out);
}